// round 4
// baseline (speedup 1.0000x reference)
#include <cuda_runtime.h>
#include <math.h>

#define B_    256
#define NH    6
#define NT    343
#define HD    32
#define CDIM  192
#define MROWS (B_*NT)          // 87808 = 686*128
#define QSCALE 0.17677669529663687f   // 32^-0.5

// ---------------- scratch (device globals; no allocation allowed) -----------
__device__ float g_q[(size_t)B_*NH*NT*HD];
__device__ float g_k[(size_t)B_*NH*NT*HD];
__device__ float g_v[(size_t)B_*NH*NT*HD];
__device__ float g_ao[(size_t)MROWS*CDIM];
__device__ float g_bias[(size_t)NH*NT*NT];

// ---------------- bias materialization: biasmat[h][q][k] --------------------
__global__ void bias_kernel(const float* __restrict__ table,
                            const int*   __restrict__ ridx) {
    int i = blockIdx.x * blockDim.x + threadIdx.x;   // over NT*NT
    if (i >= NT*NT) return;
    int idx = ridx[i];
    #pragma unroll
    for (int h = 0; h < NH; h++)
        g_bias[(size_t)h*NT*NT + i] = table[idx*NH + h];
}

// ---------------- SGEMM: C[M,Nc] = A[M,K=192] @ W[Nc,K]^T + bias ------------
// MODE 0: A = x, Nc=576, epilogue scatters to g_q/g_k/g_v (scale on q)
// MODE 1: A = g_ao, Nc=192, epilogue writes d_out
#define BM 128
#define BN 64
#define BK 16
#define ASTR 132   // smem row stride for A tile (pad: fewer store conflicts)
#define BSTR 68

template<int MODE>
__global__ void __launch_bounds__(256)
gemm_kernel(const float* __restrict__ A_in,
            const float* __restrict__ W,
            const float* __restrict__ bias,
            float*       __restrict__ out) {
    __shared__ __align__(16) float As[BK * ASTR];
    __shared__ __align__(16) float Bs[BK * BSTR];
    const float* __restrict__ A = (MODE == 0) ? A_in : g_ao;
    const int t  = threadIdx.x;
    const int m0 = blockIdx.y * BM;
    const int n0 = blockIdx.x * BN;
    const int tx = t & 15;          // col group: 4 cols
    const int ty = t >> 4;          // row group: 8 rows
    const int lrow = t >> 2;        // 0..63
    const int lk4  = (t & 3) * 4;   // 0,4,8,12

    float acc[8][4] = {};

    for (int k0 = 0; k0 < CDIM; k0 += BK) {
        float4 a0 = *(const float4*)&A[(size_t)(m0 + lrow)      * CDIM + k0 + lk4];
        float4 a1 = *(const float4*)&A[(size_t)(m0 + lrow + 64) * CDIM + k0 + lk4];
        float4 wv = *(const float4*)&W[(size_t)(n0 + lrow)      * CDIM + k0 + lk4];
        As[(lk4+0)*ASTR + lrow] = a0.x; As[(lk4+1)*ASTR + lrow] = a0.y;
        As[(lk4+2)*ASTR + lrow] = a0.z; As[(lk4+3)*ASTR + lrow] = a0.w;
        As[(lk4+0)*ASTR + lrow + 64] = a1.x; As[(lk4+1)*ASTR + lrow + 64] = a1.y;
        As[(lk4+2)*ASTR + lrow + 64] = a1.z; As[(lk4+3)*ASTR + lrow + 64] = a1.w;
        Bs[(lk4+0)*BSTR + lrow] = wv.x; Bs[(lk4+1)*BSTR + lrow] = wv.y;
        Bs[(lk4+2)*BSTR + lrow] = wv.z; Bs[(lk4+3)*BSTR + lrow] = wv.w;
        __syncthreads();
        #pragma unroll
        for (int kk = 0; kk < BK; kk++) {
            float4 av0 = *(const float4*)&As[kk*ASTR + ty*8];
            float4 av1 = *(const float4*)&As[kk*ASTR + ty*8 + 4];
            float4 bv  = *(const float4*)&Bs[kk*BSTR + tx*4];
            float a[8] = {av0.x, av0.y, av0.z, av0.w, av1.x, av1.y, av1.z, av1.w};
            float b[4] = {bv.x, bv.y, bv.z, bv.w};
            #pragma unroll
            for (int i = 0; i < 8; i++)
                #pragma unroll
                for (int j = 0; j < 4; j++)
                    acc[i][j] += a[i] * b[j];
        }
        __syncthreads();
    }

    #pragma unroll
    for (int i = 0; i < 8; i++) {
        int m = m0 + ty * 8 + i;
        #pragma unroll
        for (int j = 0; j < 4; j++) {
            int c = n0 + tx * 4 + j;
            float v = acc[i][j] + bias[c];
            if (MODE == 0) {
                int b = m / NT, n = m - b * NT;
                int s = c / CDIM;
                int hc = c - s * CDIM;
                int h = hc >> 5, d = hc & 31;
                size_t dst = ((size_t)(b * NH + h) * NT + n) * HD + d;
                if      (s == 0) g_q[dst] = v * QSCALE;
                else if (s == 1) g_k[dst] = v;
                else             g_v[dst] = v;
            } else {
                out[(size_t)m * CDIM + c] = v;
            }
        }
    }
}

// ---------------- attention: one CTA per (b,h), 8 warps --------------------
// smem: ks[NT][36] | vt[HD][348] (V transposed) | ps[8][344] | qs[8][32]
#define KSTR 36    // %32==4 -> conflict-free LDS.128 across lanes
#define VSTR 348   // byte stride 1392 %128==112 -> conflict-free LDS.128
#define PSTR 344   // 343 rounded up to multiple of 4 (zero-padded tail)
#define AT_SMEM_FLOATS (NT*KSTR + HD*VSTR + 8*PSTR + 8*32)

__global__ void __launch_bounds__(256) attn_kernel() {
    extern __shared__ float sm[];
    float* ks = sm;                    // [NT][KSTR]
    float* vt = ks + NT * KSTR;        // [HD][VSTR] transposed V
    float* ps = vt + HD * VSTR;        // [8][PSTR]
    float* qs = ps + 8 * PSTR;         // [8][32]

    const int bh = blockIdx.x;               // 0..1535
    const int b  = bh / NH, h = bh % NH;
    const size_t base = (size_t)bh * NT * HD;
    const int t = threadIdx.x;

    // stage K (stride-36, float4) and V transposed (stride-348)
    for (int i = t; i < NT * HD / 4; i += 256) {
        int e = i * 4;
        int j = e >> 5, d = e & 31;
        float4 kv = *(const float4*)&g_k[base + e];
        *(float4*)&ks[j * KSTR + d] = kv;
        float4 vv = *(const float4*)&g_v[base + e];
        vt[(d+0) * VSTR + j] = vv.x;
        vt[(d+1) * VSTR + j] = vv.y;
        vt[(d+2) * VSTR + j] = vv.z;
        vt[(d+3) * VSTR + j] = vv.w;
    }
    if (t < HD) vt[t * VSTR + NT] = 0.f;   // zero the padded V column (p=0 pairs with it)
    __syncthreads();

    const int w = t >> 5, lane = t & 31;
    const float* __restrict__ bm = &g_bias[(size_t)h * NT * NT];
    float* pw = &ps[w * PSTR];
    float* qw = &qs[w * 32];

    for (int r = w; r < NT; r += 8) {
        qw[lane] = g_q[base + (size_t)r * HD + lane];
        __syncwarp();
        float4 q4[8];
        #pragma unroll
        for (int i = 0; i < 8; i++) q4[i] = *(const float4*)&qw[i * 4];

        float sc[11];
        float mx = -1e30f;
        #pragma unroll
        for (int tt = 0; tt < 11; tt++) {
            int j = tt * 32 + lane;
            float s = -1e30f;
            if (j < NT) {
                s = bm[(size_t)r * NT + j];
                const float4* kr = (const float4*)&ks[j * KSTR];
                #pragma unroll
                for (int i = 0; i < 8; i++) {
                    float4 k4 = kr[i];
                    s += q4[i].x * k4.x;
                    s += q4[i].y * k4.y;
                    s += q4[i].z * k4.z;
                    s += q4[i].w * k4.w;
                }
            }
            sc[tt] = s;
            mx = fmaxf(mx, s);
        }
        #pragma unroll
        for (int o = 16; o; o >>= 1)
            mx = fmaxf(mx, __shfl_xor_sync(0xffffffffu, mx, o));

        float sum = 0.f;
        #pragma unroll
        for (int tt = 0; tt < 11; tt++) {
            int j = tt * 32 + lane;
            if (j < NT) {
                float e = __expf(sc[tt] - mx);
                pw[j] = e;
                sum += e;
            } else if (j < PSTR) {
                pw[j] = 0.f;
            }
        }
        #pragma unroll
        for (int o = 16; o; o >>= 1)
            sum += __shfl_xor_sync(0xffffffffu, sum, o);
        float inv = __frcp_rn(sum);
        __syncwarp();

        // P @ V : lane == output dim d, vectorized over keys
        float acc = 0.f;
        const float4* vrow = (const float4*)&vt[lane * VSTR];
        #pragma unroll 4
        for (int jj = 0; jj < PSTR / 4; jj++) {
            float4 p4 = *(const float4*)&pw[jj * 4];
            float4 v4 = vrow[jj];
            acc += p4.x * v4.x;
            acc += p4.y * v4.y;
            acc += p4.z * v4.z;
            acc += p4.w * v4.w;
        }

        g_ao[((size_t)b * NT + r) * CDIM + h * HD + lane] = acc * inv;
        __syncwarp();
    }
}

// ---------------- launch ----------------------------------------------------
extern "C" void kernel_launch(void* const* d_in, const int* in_sizes, int n_in,
                              void* d_out, int out_size) {
    const float* x      = (const float*)d_in[0];
    const float* w_qkv  = (const float*)d_in[1];
    const float* b_qkv  = (const float*)d_in[2];
    const float* w_proj = (const float*)d_in[3];
    const float* b_proj = (const float*)d_in[4];
    const float* table  = (const float*)d_in[5];
    const int*   ridx   = (const int*)d_in[6];
    float* out = (float*)d_out;

    // 1) bias gather
    bias_kernel<<<(NT*NT + 255) / 256, 256>>>(table, ridx);

    // 2) QKV GEMM (scatter epilogue)
    gemm_kernel<0><<<dim3(576 / BN, MROWS / BM), 256>>>(x, w_qkv, b_qkv, nullptr);

    // 3) attention
    const int smem_bytes = AT_SMEM_FLOATS * (int)sizeof(float);  // ~104 KB
    cudaFuncSetAttribute(attn_kernel,
                         cudaFuncAttributeMaxDynamicSharedMemorySize, smem_bytes);
    attn_kernel<<<B_ * NH, 256, smem_bytes>>>();

    // 4) output projection
    gemm_kernel<1><<<dim3(CDIM / BN, MROWS / BM), 256>>>(nullptr, w_proj, b_proj, out);
}

// round 5
// speedup vs baseline: 1.2995x; 1.2995x over previous
#include <cuda_runtime.h>
#include <math.h>

#define B_    256
#define NH    6
#define NT    343
#define HD    32
#define CDIM  192
#define MROWS (B_*NT)          // 87808 = 686*128
#define QSCALE 0.17677669529663687f   // 32^-0.5

// ---------------- scratch (device globals; no allocation allowed) -----------
__device__ float g_q[(size_t)B_*NH*NT*HD];
__device__ float g_k[(size_t)B_*NH*NT*HD];
__device__ float g_v[(size_t)B_*NH*NT*HD];
__device__ float g_ao[(size_t)MROWS*CDIM];
__device__ float g_bias[(size_t)NH*NT*NT];

// ---------------- bias materialization: biasmat[h][q][k] --------------------
__global__ void bias_kernel(const float* __restrict__ table,
                            const int*   __restrict__ ridx) {
    int i = blockIdx.x * blockDim.x + threadIdx.x;   // over NT*NT
    if (i >= NT*NT) return;
    int idx = ridx[i];
    #pragma unroll
    for (int h = 0; h < NH; h++)
        g_bias[(size_t)h*NT*NT + i] = table[idx*NH + h];
}

// ---------------- SGEMM: C[M,Nc] = A[M,K=192] @ W[Nc,K]^T + bias ------------
// Double-buffered smem stages; MODE 0 scatters qkv, MODE 1 writes d_out.
#define BM 128
#define BN 64
#define BK 16
#define ASTR 132
#define BSTR 68

template<int MODE>
__global__ void __launch_bounds__(256)
gemm_kernel(const float* __restrict__ A_in,
            const float* __restrict__ W,
            const float* __restrict__ bias,
            float*       __restrict__ out) {
    __shared__ __align__(16) float As[2][BK * ASTR];
    __shared__ __align__(16) float Bs[2][BK * BSTR];
    const float* __restrict__ A = (MODE == 0) ? A_in : g_ao;
    const int t  = threadIdx.x;
    const int m0 = blockIdx.y * BM;
    const int n0 = blockIdx.x * BN;
    const int tx = t & 15;          // col group: 4 cols
    const int ty = t >> 4;          // row group: 8 rows
    const int lrow = t >> 2;        // 0..63
    const int lk4  = (t & 3) * 4;   // 0,4,8,12

    const float* pa0 = &A[(size_t)(m0 + lrow)      * CDIM + lk4];
    const float* pa1 = &A[(size_t)(m0 + lrow + 64) * CDIM + lk4];
    const float* pw  = &W[(size_t)(n0 + lrow)      * CDIM + lk4];

    float acc[8][4] = {};

    // prologue: stage 0
    {
        float4 a0 = *(const float4*)pa0;
        float4 a1 = *(const float4*)pa1;
        float4 wv = *(const float4*)pw;
        As[0][(lk4+0)*ASTR + lrow] = a0.x; As[0][(lk4+1)*ASTR + lrow] = a0.y;
        As[0][(lk4+2)*ASTR + lrow] = a0.z; As[0][(lk4+3)*ASTR + lrow] = a0.w;
        As[0][(lk4+0)*ASTR + lrow + 64] = a1.x; As[0][(lk4+1)*ASTR + lrow + 64] = a1.y;
        As[0][(lk4+2)*ASTR + lrow + 64] = a1.z; As[0][(lk4+3)*ASTR + lrow + 64] = a1.w;
        Bs[0][(lk4+0)*BSTR + lrow] = wv.x; Bs[0][(lk4+1)*BSTR + lrow] = wv.y;
        Bs[0][(lk4+2)*BSTR + lrow] = wv.z; Bs[0][(lk4+3)*BSTR + lrow] = wv.w;
    }
    __syncthreads();

    int stage = 0;
    for (int k0 = 0; k0 < CDIM; k0 += BK) {
        float4 na0, na1, nwv;
        const bool has_next = (k0 + BK < CDIM);
        if (has_next) {
            na0 = *(const float4*)(pa0 + k0 + BK);
            na1 = *(const float4*)(pa1 + k0 + BK);
            nwv = *(const float4*)(pw  + k0 + BK);
        }
        const float* as = As[stage];
        const float* bs = Bs[stage];
        #pragma unroll
        for (int kk = 0; kk < BK; kk++) {
            float4 av0 = *(const float4*)&as[kk*ASTR + ty*8];
            float4 av1 = *(const float4*)&as[kk*ASTR + ty*8 + 4];
            float4 bv  = *(const float4*)&bs[kk*BSTR + tx*4];
            float a[8] = {av0.x, av0.y, av0.z, av0.w, av1.x, av1.y, av1.z, av1.w};
            float b[4] = {bv.x, bv.y, bv.z, bv.w};
            #pragma unroll
            for (int i = 0; i < 8; i++)
                #pragma unroll
                for (int j = 0; j < 4; j++)
                    acc[i][j] += a[i] * b[j];
        }
        if (has_next) {
            const int ns = stage ^ 1;
            As[ns][(lk4+0)*ASTR + lrow] = na0.x; As[ns][(lk4+1)*ASTR + lrow] = na0.y;
            As[ns][(lk4+2)*ASTR + lrow] = na0.z; As[ns][(lk4+3)*ASTR + lrow] = na0.w;
            As[ns][(lk4+0)*ASTR + lrow + 64] = na1.x; As[ns][(lk4+1)*ASTR + lrow + 64] = na1.y;
            As[ns][(lk4+2)*ASTR + lrow + 64] = na1.z; As[ns][(lk4+3)*ASTR + lrow + 64] = na1.w;
            Bs[ns][(lk4+0)*BSTR + lrow] = nwv.x; Bs[ns][(lk4+1)*BSTR + lrow] = nwv.y;
            Bs[ns][(lk4+2)*BSTR + lrow] = nwv.z; Bs[ns][(lk4+3)*BSTR + lrow] = nwv.w;
            __syncthreads();
        }
        stage ^= 1;
    }

    #pragma unroll
    for (int i = 0; i < 8; i++) {
        int m = m0 + ty * 8 + i;
        #pragma unroll
        for (int j = 0; j < 4; j++) {
            int c = n0 + tx * 4 + j;
            float v = acc[i][j] + bias[c];
            if (MODE == 0) {
                int b = m / NT, n = m - b * NT;
                int s = c / CDIM;
                int hc = c - s * CDIM;
                int h = hc >> 5, d = hc & 31;
                size_t dst = ((size_t)(b * NH + h) * NT + n) * HD + d;
                if      (s == 0) g_q[dst] = v * QSCALE;
                else if (s == 1) g_k[dst] = v;
                else             g_v[dst] = v;
            } else {
                out[(size_t)m * CDIM + c] = v;
            }
        }
    }
}

// ---------------- attention: one CTA per (b,h), 8 warps, 2 rows/warp --------
#define KSTR 36    // %32==4 -> conflict-free LDS.128 across lanes
#define VSTR 348   // conflict-free LDS.128 (4L mod-32 tiling)
#define PSTR 344   // 343 rounded to multiple of 4, zero-padded tail
#define AT_SMEM_FLOATS (NT*KSTR + HD*VSTR + 8*2*PSTR + 8*2*32)

template<int NR>
__device__ __forceinline__ void attn_rows(
    int r0, const float* __restrict__ ks, const float* __restrict__ vt,
    float* __restrict__ pw,   // [NR][PSTR]
    float* __restrict__ qw,   // [NR][32]
    const float* __restrict__ bm, size_t base, int b, int h, int lane)
{
    // stage q rows
    #pragma unroll
    for (int rr = 0; rr < NR; rr++)
        qw[rr*32 + lane] = g_q[base + (size_t)(r0+rr) * HD + lane];
    __syncwarp();
    float4 q4[NR][8];
    #pragma unroll
    for (int rr = 0; rr < NR; rr++)
        #pragma unroll
        for (int i = 0; i < 8; i++)
            q4[rr][i] = *(const float4*)&qw[rr*32 + i*4];

    float sc[NR][11];
    float mx[NR];
    #pragma unroll
    for (int rr = 0; rr < NR; rr++) mx[rr] = -1e30f;

    #pragma unroll
    for (int tt = 0; tt < 11; tt++) {
        int j = tt * 32 + lane;
        float s[NR];
        if (j < NT) {
            #pragma unroll
            for (int rr = 0; rr < NR; rr++)
                s[rr] = bm[(size_t)(r0+rr) * NT + j];
            const float4* kr = (const float4*)&ks[j * KSTR];
            #pragma unroll
            for (int i = 0; i < 8; i++) {
                float4 k4 = kr[i];
                #pragma unroll
                for (int rr = 0; rr < NR; rr++) {
                    s[rr] += q4[rr][i].x * k4.x;
                    s[rr] += q4[rr][i].y * k4.y;
                    s[rr] += q4[rr][i].z * k4.z;
                    s[rr] += q4[rr][i].w * k4.w;
                }
            }
        } else {
            #pragma unroll
            for (int rr = 0; rr < NR; rr++) s[rr] = -1e30f;
        }
        #pragma unroll
        for (int rr = 0; rr < NR; rr++) {
            sc[rr][tt] = s[rr];
            mx[rr] = fmaxf(mx[rr], s[rr]);
        }
    }
    #pragma unroll
    for (int rr = 0; rr < NR; rr++)
        #pragma unroll
        for (int o = 16; o; o >>= 1)
            mx[rr] = fmaxf(mx[rr], __shfl_xor_sync(0xffffffffu, mx[rr], o));

    float sum[NR];
    #pragma unroll
    for (int rr = 0; rr < NR; rr++) sum[rr] = 0.f;
    #pragma unroll
    for (int tt = 0; tt < 11; tt++) {
        int j = tt * 32 + lane;
        #pragma unroll
        for (int rr = 0; rr < NR; rr++) {
            if (j < NT) {
                float e = __expf(sc[rr][tt] - mx[rr]);
                pw[rr*PSTR + j] = e;
                sum[rr] += e;
            } else if (j < PSTR) {
                pw[rr*PSTR + j] = 0.f;
            }
        }
    }
    float inv[NR];
    #pragma unroll
    for (int rr = 0; rr < NR; rr++) {
        #pragma unroll
        for (int o = 16; o; o >>= 1)
            sum[rr] += __shfl_xor_sync(0xffffffffu, sum[rr], o);
        inv[rr] = __frcp_rn(sum[rr]);
    }
    __syncwarp();

    // P @ V : lane == output dim d; V row loaded once per NR rows
    float acc[NR];
    #pragma unroll
    for (int rr = 0; rr < NR; rr++) acc[rr] = 0.f;
    const float4* vrow = (const float4*)&vt[lane * VSTR];
    #pragma unroll 2
    for (int jj = 0; jj < PSTR / 4; jj++) {
        float4 v4 = vrow[jj];
        #pragma unroll
        for (int rr = 0; rr < NR; rr++) {
            float4 p4 = *(const float4*)&pw[rr*PSTR + jj*4];
            acc[rr] += p4.x * v4.x;
            acc[rr] += p4.y * v4.y;
            acc[rr] += p4.z * v4.z;
            acc[rr] += p4.w * v4.w;
        }
    }
    #pragma unroll
    for (int rr = 0; rr < NR; rr++)
        g_ao[((size_t)b * NT + (r0+rr)) * CDIM + h * HD + lane] = acc[rr] * inv[rr];
    __syncwarp();
}

__global__ void __launch_bounds__(256) attn_kernel() {
    extern __shared__ float sm[];
    float* ks = sm;                    // [NT][KSTR]
    float* vt = ks + NT * KSTR;        // [HD][VSTR] transposed V
    float* ps = vt + HD * VSTR;        // [8][2][PSTR]
    float* qs = ps + 8 * 2 * PSTR;     // [8][2][32]

    const int bh = blockIdx.x;               // 0..1535
    const int b  = bh / NH, h = bh % NH;
    const size_t base = (size_t)bh * NT * HD;
    const int t = threadIdx.x;

    // stage K (stride-36, float4) and V transposed (stride-348)
    for (int i = t; i < NT * HD / 4; i += 256) {
        int e = i * 4;
        int j = e >> 5, d = e & 31;
        float4 kv = *(const float4*)&g_k[base + e];
        *(float4*)&ks[j * KSTR + d] = kv;
        float4 vv = *(const float4*)&g_v[base + e];
        vt[(d+0) * VSTR + j] = vv.x;
        vt[(d+1) * VSTR + j] = vv.y;
        vt[(d+2) * VSTR + j] = vv.z;
        vt[(d+3) * VSTR + j] = vv.w;
    }
    if (t < HD) vt[t * VSTR + NT] = 0.f;   // zero padded V column
    __syncthreads();

    const int w = t >> 5, lane = t & 31;
    const float* __restrict__ bm = &g_bias[(size_t)h * NT * NT];
    float* pw = &ps[w * 2 * PSTR];
    float* qw = &qs[w * 2 * 32];

    // pairs: rows (2w+16k, 2w+16k+1) cover 0..341; row 342 handled by warp 3
    for (int r = 2 * w; r < NT - 1; r += 16)
        attn_rows<2>(r, ks, vt, pw, qw, bm, base, b, h, lane);
    if (w == 3)   // 342 mod 16 = 6 -> warp 3's residue class, keeps it off hot warps
        attn_rows<1>(NT - 1, ks, vt, pw, qw, bm, base, b, h, lane);
}

// ---------------- launch ----------------------------------------------------
extern "C" void kernel_launch(void* const* d_in, const int* in_sizes, int n_in,
                              void* d_out, int out_size) {
    const float* x      = (const float*)d_in[0];
    const float* w_qkv  = (const float*)d_in[1];
    const float* b_qkv  = (const float*)d_in[2];
    const float* w_proj = (const float*)d_in[3];
    const float* b_proj = (const float*)d_in[4];
    const float* table  = (const float*)d_in[5];
    const int*   ridx   = (const int*)d_in[6];
    float* out = (float*)d_out;

    // 1) bias gather
    bias_kernel<<<(NT*NT + 255) / 256, 256>>>(table, ridx);

    // 2) QKV GEMM (scatter epilogue)
    gemm_kernel<0><<<dim3(576 / BN, MROWS / BM), 256>>>(x, w_qkv, b_qkv, nullptr);

    // 3) attention
    const int smem_bytes = AT_SMEM_FLOATS * (int)sizeof(float);  // ~117 KB
    cudaFuncSetAttribute(attn_kernel,
                         cudaFuncAttributeMaxDynamicSharedMemorySize, smem_bytes);
    attn_kernel<<<B_ * NH, 256, smem_bytes>>>();

    // 4) output projection
    gemm_kernel<1><<<dim3(CDIM / BN, MROWS / BM), 256>>>(nullptr, w_proj, b_proj, out);
}